// round 3
// baseline (speedup 1.0000x reference)
#include <cuda_runtime.h>
#include <math.h>

// Problem constants
#define B_    16
#define T_    1000
#define INDIM 257
#define FEAT  771
#define H_    512
#define H3    1536
#define KN    9
#define KS    6
#define M_    (B_*T_)        // 16000
#define FOUT  (H_*KN)        // 4608
#define LDW   260            // padded cols for packed W_out slice
#define PF    8              // scan prefetch depth

// ---------------- scratch (device globals; no runtime allocation) ------------
__device__ float g_X0[T_*B_*H_];        // (T,B,H) after input layer
__device__ float g_U [T_*B_*H3];        // (T,B,3H) SRU pre-activations
__device__ float g_X1[T_*B_*H_];        // SRU layer-1 output
__device__ float g_X2[T_*B_*H_];        // SRU layer-2 output
__device__ float g_hmax[B_*KN*T_*H_];   // conv+tanh+h-pool output (B,KN,T,H)
__device__ float g_Y [M_*FOUT];         // pooled, transposed to (B*T, H*KN)
__device__ float g_Wp[FOUT*LDW];        // packed W_out[:, 257:514], zero-padded

__device__ __forceinline__ float sigf(float x) { return 1.f / (1.f + __expf(-x)); }

// ---- packed f32x2 helpers (FFMA2: ptxas never emits this from C++) ----------
__device__ __forceinline__ unsigned long long pack2(float lo, float hi) {
    unsigned long long r;
    asm("mov.b64 %0, {%1, %2};" : "=l"(r) : "f"(lo), "f"(hi));
    return r;
}
__device__ __forceinline__ void fma2(unsigned long long& d,
                                     unsigned long long a, unsigned long long b) {
    asm("fma.rn.f32x2 %0, %1, %2, %3;" : "=l"(d) : "l"(a), "l"(b), "l"(d));
}
__device__ __forceinline__ float2 unpack2(unsigned long long v) {
    float lo, hi;
    asm("mov.b64 {%0, %1}, %2;" : "=f"(lo), "=f"(hi) : "l"(v));
    return make_float2(lo, hi);
}

// ---------------- 128x128x8 SGEMM, 256 threads, 8x8 microtile, FFMA2 ---------
// A: MxK row-major (lda=K), B: KxN row-major (ldb), M % 128 == 0.
// MODE 0: C[r*N + c] = acc
// MODE 1: C[((r%T)*B + r/T)*H + c] = tanh(acc + bias[c])   (time-major store)
// MODE 2: C[r*INDIM + c] = sigmoid(acc+bias[c]) * gate[r*FEAT + INDIM + c], c<N
template <int MODE>
__global__ __launch_bounds__(256) void sgemm_k(
    const float* __restrict__ A, const float* __restrict__ Bm,
    float* __restrict__ C, int N, int K, int ldb, int Nld,
    const float* __restrict__ bias, const float* __restrict__ gate)
{
    __shared__ float As[8][132];
    __shared__ float Bs[8][128];

    const int tid     = threadIdx.x;
    const int rowBase = blockIdx.y * 128;
    const int colBase = blockIdx.x * 128;

    const int aRow = tid >> 1;
    const int aCol = (tid & 1) * 4;
    const int bRow = tid >> 5;
    const int bCol = (tid & 31) * 4;

    const int tRow = (tid >> 4) * 8;
    const int tCol = (tid & 15) * 8;

    unsigned long long acc2[8][4];
    #pragma unroll
    for (int i = 0; i < 8; ++i)
        #pragma unroll
        for (int j = 0; j < 4; ++j) acc2[i][j] = 0ull;

    const float* Aptr = A + (size_t)(rowBase + aRow) * K;

    for (int k0 = 0; k0 < K; k0 += 8) {
        float a0 = 0.f, a1 = 0.f, a2 = 0.f, a3 = 0.f;
        {
            int gk = k0 + aCol;
            if (gk + 3 < K) {
                a0 = Aptr[gk]; a1 = Aptr[gk+1]; a2 = Aptr[gk+2]; a3 = Aptr[gk+3];
            } else {
                if (gk     < K) a0 = Aptr[gk];
                if (gk + 1 < K) a1 = Aptr[gk+1];
                if (gk + 2 < K) a2 = Aptr[gk+2];
                if (gk + 3 < K) a3 = Aptr[gk+3];
            }
        }
        float4 bv = make_float4(0.f, 0.f, 0.f, 0.f);
        {
            int gkb = k0 + bRow;
            int gc  = colBase + bCol;
            if (gkb < K && gc < Nld)
                bv = *(const float4*)(Bm + (size_t)gkb * ldb + gc);
        }
        __syncthreads();
        As[aCol+0][aRow] = a0;
        As[aCol+1][aRow] = a1;
        As[aCol+2][aRow] = a2;
        As[aCol+3][aRow] = a3;
        *(float4*)&Bs[bRow][bCol] = bv;
        __syncthreads();

        #pragma unroll
        for (int kk = 0; kk < 8; ++kk) {
            float4 arl = *(const float4*)&As[kk][tRow];
            float4 arh = *(const float4*)&As[kk][tRow + 4];
            float ar[8] = {arl.x, arl.y, arl.z, arl.w, arh.x, arh.y, arh.z, arh.w};
            const unsigned long long* bp =
                (const unsigned long long*)&Bs[kk][tCol];
            unsigned long long b0 = bp[0], b1 = bp[1], b2 = bp[2], b3 = bp[3];
            #pragma unroll
            for (int i = 0; i < 8; ++i) {
                unsigned long long ad = pack2(ar[i], ar[i]);
                fma2(acc2[i][0], ad, b0);
                fma2(acc2[i][1], ad, b1);
                fma2(acc2[i][2], ad, b2);
                fma2(acc2[i][3], ad, b3);
            }
        }
    }

    // ---- epilogue
    #pragma unroll
    for (int i = 0; i < 8; ++i) {
        int r = rowBase + tRow + i;
        float row[8];
        #pragma unroll
        for (int j = 0; j < 4; ++j) {
            float2 v = unpack2(acc2[i][j]);
            row[2*j] = v.x; row[2*j+1] = v.y;
        }
        if (MODE == 0) {
            float* Cp = C + (size_t)r * N + colBase + tCol;
            #pragma unroll
            for (int j = 0; j < 8; ++j) Cp[j] = row[j];
        } else if (MODE == 1) {
            int orow = (r % T_) * B_ + (r / T_);
            float* Cp = C + (size_t)orow * H_;
            #pragma unroll
            for (int j = 0; j < 8; ++j) {
                int cidx = colBase + tCol + j;
                Cp[cidx] = tanhf(row[j] + bias[cidx]);
            }
        } else {
            #pragma unroll
            for (int j = 0; j < 8; ++j) {
                int cidx = colBase + tCol + j;
                if (cidx < N) {
                    float s = sigf(row[j] + bias[cidx]);
                    C[(size_t)r * INDIM + cidx] = s * gate[(size_t)r * FEAT + INDIM + cidx];
                }
            }
        }
    }
}

// ---------------- SRU recurrence: 1 thread/(b,h), depth-8 rolling prefetch ----
__global__ __launch_bounds__(64) void sru_scan(
    const float* __restrict__ U, const float* __restrict__ X,
    float* __restrict__ Xout,
    const float* __restrict__ v, const float* __restrict__ bb)
{
    int g = blockIdx.x * 64 + threadIdx.x;   // 0..B*H-1
    int b = g / H_, h = g % H_;
    const float vf = v[h],  vr = v[H_ + h];
    const float bf = bb[h], br = bb[H_ + h];
    const float* Ub = U + b * H3 + h;
    const float* Xb = X + b * H_ + h;
    float*       Ob = Xout + b * H_ + h;

    float pxt[PF], pfp[PF], prp[PF], pxin[PF];
    #pragma unroll
    for (int i = 0; i < PF; ++i) {
        const float* Un = Ub + (size_t)i * B_ * H3;
        pxt[i]  = Un[0]; pfp[i] = Un[H_]; prp[i] = Un[2 * H_];
        pxin[i] = Xb[(size_t)i * B_ * H_];
    }

    float c = 0.f;
    for (int t0 = 0; t0 < T_; t0 += PF) {
        #pragma unroll
        for (int i = 0; i < PF; ++i) {
            int t = t0 + i;
            float xt = pxt[i], fp = pfp[i], rp = prp[i], xin = pxin[i];
            // refill slot i for step t+PF (issued early, consumed PF steps later)
            int tp = t + PF;
            if (tp < T_) {
                const float* Un = Ub + (size_t)tp * B_ * H3;
                pxt[i]  = Un[0]; pfp[i] = Un[H_]; prp[i] = Un[2 * H_];
                pxin[i] = Xb[(size_t)tp * B_ * H_];
            }
            float f  = sigf(fp + vf * c + bf);
            float rr = sigf(rp + vr * c + br);
            float cn = f * c + (1.f - f) * xt;
            Ob[(size_t)t * B_ * H_] = rr * cn + (1.f - rr) * xin;
            c = cn;
        }
    }
}

// -------- fused conv 6x6 (9ch, pad 3/2) + bias + tanh + h-direction 3-max ----
// One block = one (t,b) pair, 512 threads = full H row.
__global__ __launch_bounds__(512) void conv_pool_h(
    const float* __restrict__ X,   // (T,B,H)
    const float* __restrict__ Wk,  // (9,1,6,6)
    const float* __restrict__ cb,  // (9)
    float* __restrict__ out)       // h-pooled conv (B,KN,T,H)
{
    __shared__ float sw[KN * KS * KS];          // 324
    __shared__ float xs[KS][H_ + 6];            // rows t-3..t+2, h padded by 3/2+1
    __shared__ float buf[KN][H_ + 2];           // conv row, padded for pool

    int h = threadIdx.x;
    int t = blockIdx.x;
    int b = blockIdx.y;

    for (int i = h; i < KN * KS * KS; i += 512) sw[i] = Wk[i];

    // stage 6 input rows with h-halo [-3, 514]
    #pragma unroll
    for (int p = 0; p < KS; ++p) {
        int tt = t - 3 + p;
        const float* row = X + (size_t)(tt * B_ + b) * H_;
        bool tok = (tt >= 0 && tt < T_);
        // each thread fills index h and strided extras for the 6-wide halo
        for (int idx = h; idx < H_ + 6; idx += 512) {
            int hh = idx - 3;
            xs[p][idx] = (tok && hh >= 0 && hh < H_) ? row[hh] : 0.f;
        }
    }
    if (h < KN) { buf[h][0] = -INFINITY; buf[h][H_ + 1] = -INFINITY; }
    __syncthreads();

    float acc[KN];
    #pragma unroll
    for (int o = 0; o < KN; ++o) acc[o] = 0.f;

    #pragma unroll
    for (int p = 0; p < KS; ++p) {
        float xv[KS];
        #pragma unroll
        for (int q = 0; q < KS; ++q) xv[q] = xs[p][h + q];
        #pragma unroll
        for (int q = 0; q < KS; ++q) {
            float x = xv[q];
            #pragma unroll
            for (int o = 0; o < KN; ++o)
                acc[o] = fmaf(x, sw[o * 36 + p * 6 + q], acc[o]);
        }
    }
    #pragma unroll
    for (int o = 0; o < KN; ++o) buf[o][h + 1] = tanhf(acc[o] + cb[o]);
    __syncthreads();

    #pragma unroll
    for (int o = 0; o < KN; ++o) {
        float m = fmaxf(fmaxf(buf[o][h], buf[o][h + 1]), buf[o][h + 2]);
        out[((size_t)(b * KN + o) * T_ + t) * H_ + h] = m;
    }
}

// t-direction max + transpose into (B*T, H*KN) with feature = h*KN + o
__global__ void pool_t(const float* __restrict__ in, float* __restrict__ Y)
{
    int h  = blockIdx.x * blockDim.x + threadIdx.x;
    int t  = blockIdx.y;
    int bk = blockIdx.z;
    int b  = bk / KN, o = bk % KN;
    size_t base = ((size_t)bk * T_ + t) * H_ + h;
    float m = in[base];
    if (t > 0)      m = fmaxf(m, in[base - H_]);
    if (t < T_ - 1) m = fmaxf(m, in[base + H_]);
    Y[((size_t)(b * T_ + t)) * FOUT + h * KN + o] = m;
}

// ---------------- pack W_out[:, 257:514] into (4608 x 260) -------------------
__global__ void pack_w(const float* __restrict__ Wout, float* __restrict__ Wp)
{
    int i = blockIdx.x * blockDim.x + threadIdx.x;
    if (i >= FOUT * LDW) return;
    int k = i / LDW, j = i % LDW;
    Wp[i] = (j < INDIM) ? Wout[(size_t)k * FEAT + INDIM + j] : 0.f;
}

// ---------------- launch ------------------------------------------------------
extern "C" void kernel_launch(void* const* d_in, const int* in_sizes, int n_in,
                              void* d_out, int out_size)
{
    const float* inputs = (const float*)d_in[0];
    const float* W_in   = (const float*)d_in[1];
    const float* b_in   = (const float*)d_in[2];
    const float* W_rnn  = (const float*)d_in[3];
    const float* v_rnn  = (const float*)d_in[4];
    const float* b_rnn  = (const float*)d_in[5];
    const float* conv_k = (const float*)d_in[6];
    const float* conv_b = (const float*)d_in[7];
    const float* W_out  = (const float*)d_in[8];
    const float* b_out  = (const float*)d_in[9];
    float* out = (float*)d_out;

    float *X0, *U, *X1, *X2, *HM, *Y, *Wp;
    cudaGetSymbolAddress((void**)&X0, g_X0);
    cudaGetSymbolAddress((void**)&U,  g_U);
    cudaGetSymbolAddress((void**)&X1, g_X1);
    cudaGetSymbolAddress((void**)&X2, g_X2);
    cudaGetSymbolAddress((void**)&HM, g_hmax);
    cudaGetSymbolAddress((void**)&Y,  g_Y);
    cudaGetSymbolAddress((void**)&Wp, g_Wp);

    pack_w<<<(FOUT * LDW + 255) / 256, 256>>>(W_out, Wp);

    // input layer: tanh(inputs @ W_in + b_in), stored time-major (T,B,H)
    sgemm_k<1><<<dim3(H_ / 128, M_ / 128), 256>>>(
        inputs, W_in, X0, H_, FEAT, H_, H_, b_in, nullptr);

    // SRU layer 0
    sgemm_k<0><<<dim3(H3 / 128, M_ / 128), 256>>>(
        X0, W_rnn, U, H3, H_, H3, H3, nullptr, nullptr);
    sru_scan<<<(B_ * H_) / 64, 64>>>(U, X0, X1, v_rnn, b_rnn);

    // SRU layer 1
    sgemm_k<0><<<dim3(H3 / 128, M_ / 128), 256>>>(
        X1, W_rnn + H_ * H3, U, H3, H_, H3, H3, nullptr, nullptr);
    sru_scan<<<(B_ * H_) / 64, 64>>>(U, X1, X2, v_rnn + 2 * H_, b_rnn + 2 * H_);

    // fused conv + bias + tanh + h-pool
    conv_pool_h<<<dim3(T_, B_), 512>>>(X2, conv_k, conv_b, HM);

    // t-pool + transpose to (B*T, H*KN)
    pool_t<<<dim3(H_ / 256, T_, B_ * KN), 256>>>(HM, Y);

    // output GEMM on the 257-column slice + sigmoid gate * inputs
    sgemm_k<2><<<dim3((INDIM + 127) / 128, M_ / 128), 256>>>(
        Y, Wp, out, INDIM, FOUT, LDW, LDW, b_out + INDIM, inputs);
}

// round 5
// speedup vs baseline: 2.6228x; 2.6228x over previous
#include <cuda_runtime.h>
#include <cuda_bf16.h>
#include <math.h>
#include <stdint.h>

// Problem constants
#define B_    16
#define T_    1000
#define INDIM 257
#define FEAT  771
#define H_    512
#define H3    1536
#define KN    9
#define KS    6
#define M_    (B_*T_)        // 16000
#define FOUT  (H_*KN)        // 4608
#define PF    10             // scan prefetch depth

// ---------------- scratch (device globals; no runtime allocation) ------------
__device__ float g_X0[T_*B_*H_];
__device__ float g_U [T_*B_*H3];
__device__ float g_X1[T_*B_*H_];
__device__ float g_X2[T_*B_*H_];
__device__ float g_hmax[B_*KN*T_*H_];
__device__ float g_Y [M_*FOUT];
// bf16 hi/lo weight copies, K-major (N rows x Kp cols), zero-padded
__device__ __nv_bfloat16 g_BinH [512*800],     g_BinL [512*800];
__device__ __nv_bfloat16 g_BrnnH[2*1536*512],  g_BrnnL[2*1536*512];
__device__ __nv_bfloat16 g_BoutH[384*4608],    g_BoutL[384*4608];

__device__ __forceinline__ float sigf(float x) { return 1.f / (1.f + __expf(-x)); }

__device__ __forceinline__ uint32_t pk(__nv_bfloat16 a, __nv_bfloat16 b) {
    return (uint32_t)__bfloat16_as_ushort(b) << 16 | __bfloat16_as_ushort(a);
}
__device__ __forceinline__ void mma16816(float* d, const uint32_t* a,
                                         const uint32_t* b) {
    asm volatile(
        "mma.sync.aligned.m16n8k16.row.col.f32.bf16.bf16.f32 "
        "{%0,%1,%2,%3}, {%4,%5,%6,%7}, {%8,%9}, {%0,%1,%2,%3};"
        : "+f"(d[0]), "+f"(d[1]), "+f"(d[2]), "+f"(d[3])
        : "r"(a[0]), "r"(a[1]), "r"(a[2]), "r"(a[3]), "r"(b[0]), "r"(b[1]));
}

// ---------------- tensor-core GEMM (mma.sync bf16, 2-term fp32 split) --------
// C(M x N) = A(M x Kreal fp32, lda) * B^T, B given K-major as bf16 hi/lo.
// Block 128x128, BK=32 fp32. Smem word layout: idx = row*16 + (w ^ 2*(row&7)).
// MODE 0: C[r*ldc + c] = acc
// MODE 1: C[((r%T)*B + r/T)*H_ + c] = tanh(acc + bias[c])
// MODE 2: c<Ncols: C[r*INDIM + c] = sig(acc+bias[c]) * gate[r*FEAT+INDIM+c]
template <int MODE>
__global__ __launch_bounds__(256) void hgemm(
    const float* __restrict__ A,
    const __nv_bfloat16* __restrict__ Bh, const __nv_bfloat16* __restrict__ Bl,
    float* __restrict__ C, int Kreal, int Kp, int lda, int ldc, int Ncols,
    const float* __restrict__ bias, const float* __restrict__ gate)
{
    __shared__ uint32_t Ah_s[128*16], Al_s[128*16];
    __shared__ uint32_t Bh_s[128*16], Bl_s[128*16];

    const int tid  = threadIdx.x;
    const int m0   = blockIdx.y * 128;
    const int n0   = blockIdx.x * 128;
    const int wid  = tid >> 5, lane = tid & 31;
    const int wm   = wid >> 2, wn = wid & 3;       // 2 x 4 warp grid
    const int quad = lane >> 2, qc = lane & 3;
    const int swq  = quad << 1;                    // frag-load swizzle

    const int row = tid >> 1, hf = tid & 1;        // staging assignment
    const float* Arow = A + (size_t)(m0 + row) * lda + hf * 16;
    const __nv_bfloat16* BhR = Bh + (size_t)(n0 + row) * Kp + hf * 16;
    const __nv_bfloat16* BlR = Bl + (size_t)(n0 + row) * Kp + hf * 16;
    const bool vec = ((lda & 3) == 0) && (Kreal == Kp);

    float acc[4][4][4];
    #pragma unroll
    for (int i = 0; i < 4; ++i)
        #pragma unroll
        for (int j = 0; j < 4; ++j)
            #pragma unroll
            for (int q = 0; q < 4; ++q) acc[i][j][q] = 0.f;

    float ar[16];
    uint4 bhv[2], blv[2];

    // prefetch chunk 0
    {
        if (vec) {
            const float4* p = (const float4*)Arow;
            float4 v0 = p[0], v1 = p[1], v2 = p[2], v3 = p[3];
            ar[0]=v0.x; ar[1]=v0.y; ar[2]=v0.z; ar[3]=v0.w;
            ar[4]=v1.x; ar[5]=v1.y; ar[6]=v1.z; ar[7]=v1.w;
            ar[8]=v2.x; ar[9]=v2.y; ar[10]=v2.z; ar[11]=v2.w;
            ar[12]=v3.x; ar[13]=v3.y; ar[14]=v3.z; ar[15]=v3.w;
        } else {
            #pragma unroll
            for (int t = 0; t < 16; ++t)
                ar[t] = (hf * 16 + t < Kreal) ? Arow[t] : 0.f;
        }
        bhv[0] = ((const uint4*)BhR)[0]; bhv[1] = ((const uint4*)BhR)[1];
        blv[0] = ((const uint4*)BlR)[0]; blv[1] = ((const uint4*)BlR)[1];
    }

    const int nchunks = Kp / 32;
    const int sw_r = (row & 7) << 1;

    for (int ic = 0; ic < nchunks; ++ic) {
        __syncthreads();   // previous MMA phase done reading smem
        // ---- stage: convert A, copy B
        #pragma unroll
        for (int j = 0; j < 8; ++j) {
            float a0 = ar[2*j], a1 = ar[2*j+1];
            __nv_bfloat16 h0 = __float2bfloat16(a0);
            __nv_bfloat16 h1 = __float2bfloat16(a1);
            __nv_bfloat16 l0 = __float2bfloat16(a0 - __bfloat162float(h0));
            __nv_bfloat16 l1 = __float2bfloat16(a1 - __bfloat162float(h1));
            const int idx = row * 16 + ((hf * 8 + j) ^ sw_r);
            Ah_s[idx] = pk(h0, h1);
            Al_s[idx] = pk(l0, l1);
        }
        {
            const uint32_t* bw = (const uint32_t*)bhv;
            const uint32_t* cw = (const uint32_t*)blv;
            #pragma unroll
            for (int j = 0; j < 8; ++j) {
                const int idx = row * 16 + ((hf * 8 + j) ^ sw_r);
                Bh_s[idx] = bw[j];
                Bl_s[idx] = cw[j];
            }
        }
        __syncthreads();

        // ---- prefetch next chunk
        if (ic + 1 < nchunks) {
            const int k0 = (ic + 1) * 32;
            if (vec) {
                const float4* p = (const float4*)(Arow + k0);
                float4 v0 = p[0], v1 = p[1], v2 = p[2], v3 = p[3];
                ar[0]=v0.x; ar[1]=v0.y; ar[2]=v0.z; ar[3]=v0.w;
                ar[4]=v1.x; ar[5]=v1.y; ar[6]=v1.z; ar[7]=v1.w;
                ar[8]=v2.x; ar[9]=v2.y; ar[10]=v2.z; ar[11]=v2.w;
                ar[12]=v3.x; ar[13]=v3.y; ar[14]=v3.z; ar[15]=v3.w;
            } else {
                #pragma unroll
                for (int t = 0; t < 16; ++t)
                    ar[t] = (k0 + hf * 16 + t < Kreal) ? Arow[k0 + t] : 0.f;
            }
            bhv[0] = ((const uint4*)(BhR + k0))[0];
            bhv[1] = ((const uint4*)(BhR + k0))[1];
            blv[0] = ((const uint4*)(BlR + k0))[0];
            blv[1] = ((const uint4*)(BlR + k0))[1];
        }

        // ---- MMA phase: 2 k-tiles of 16
        #pragma unroll
        for (int kt = 0; kt < 2; ++kt) {
            const int w0 = kt * 8 + qc, w1 = kt * 8 + 4 + qc;
            uint32_t af[4][4], alf[4][4];
            #pragma unroll
            for (int i = 0; i < 4; ++i) {
                const int r0 = wm * 64 + i * 16 + quad, r1 = r0 + 8;
                const int i00 = r0*16 + (w0^swq), i10 = r1*16 + (w0^swq);
                const int i01 = r0*16 + (w1^swq), i11 = r1*16 + (w1^swq);
                af[i][0]=Ah_s[i00]; af[i][1]=Ah_s[i10];
                af[i][2]=Ah_s[i01]; af[i][3]=Ah_s[i11];
                alf[i][0]=Al_s[i00]; alf[i][1]=Al_s[i10];
                alf[i][2]=Al_s[i01]; alf[i][3]=Al_s[i11];
            }
            uint32_t bfh[4][2], bfl[4][2];
            #pragma unroll
            for (int j = 0; j < 4; ++j) {
                const int rn = wn * 32 + j * 8 + quad;
                const int i0 = rn*16 + (w0^swq), i1 = rn*16 + (w1^swq);
                bfh[j][0]=Bh_s[i0]; bfh[j][1]=Bh_s[i1];
                bfl[j][0]=Bl_s[i0]; bfl[j][1]=Bl_s[i1];
            }
            #pragma unroll
            for (int i = 0; i < 4; ++i)
                #pragma unroll
                for (int j = 0; j < 4; ++j) {
                    mma16816(acc[i][j], af[i],  bfh[j]);
                    mma16816(acc[i][j], af[i],  bfl[j]);
                    mma16816(acc[i][j], alf[i], bfh[j]);
                }
        }
    }

    // ---- epilogue
    #pragma unroll
    for (int i = 0; i < 4; ++i) {
        #pragma unroll
        for (int j = 0; j < 4; ++j) {
            const int r0 = m0 + wm * 64 + i * 16 + quad, r1 = r0 + 8;
            const int cc = n0 + wn * 32 + j * 8 + 2 * qc;
            const float* d = acc[i][j];
            if (MODE == 0) {
                *(float2*)(C + (size_t)r0 * ldc + cc) = make_float2(d[0], d[1]);
                *(float2*)(C + (size_t)r1 * ldc + cc) = make_float2(d[2], d[3]);
            } else if (MODE == 1) {
                const int o0 = (r0 % T_) * B_ + (r0 / T_);
                const int o1 = (r1 % T_) * B_ + (r1 / T_);
                const float b0 = bias[cc], b1 = bias[cc + 1];
                *(float2*)(C + (size_t)o0 * H_ + cc) =
                    make_float2(tanhf(d[0] + b0), tanhf(d[1] + b1));
                *(float2*)(C + (size_t)o1 * H_ + cc) =
                    make_float2(tanhf(d[2] + b0), tanhf(d[3] + b1));
            } else {
                #pragma unroll
                for (int q = 0; q < 2; ++q) {
                    const int c = cc + q;
                    if (c < Ncols) {
                        float s0 = sigf(d[q] + bias[c]);
                        float s1 = sigf(d[2 + q] + bias[c]);
                        C[(size_t)r0 * INDIM + c] =
                            s0 * gate[(size_t)r0 * FEAT + INDIM + c];
                        C[(size_t)r1 * INDIM + c] =
                            s1 * gate[(size_t)r1 * FEAT + INDIM + c];
                    }
                }
            }
        }
    }
}

// ---------------- weight prep: transpose to K-major + bf16 hi/lo split -------
__global__ void prep_w(const float* __restrict__ W, __nv_bfloat16* __restrict__ Bh,
                       __nv_bfloat16* __restrict__ Bl, int K, int N, int Kp)
{
    int i = blockIdx.x * blockDim.x + threadIdx.x;
    if (i >= N * Kp) return;
    int n = i / Kp, k = i % Kp;
    float v = (k < K) ? W[(size_t)k * N + n] : 0.f;
    __nv_bfloat16 h = __float2bfloat16(v);
    Bh[i] = h;
    Bl[i] = __float2bfloat16(v - __bfloat162float(h));
}
__global__ void prep_wout(const float* __restrict__ Wout,
                          __nv_bfloat16* __restrict__ Bh,
                          __nv_bfloat16* __restrict__ Bl)
{
    int i = blockIdx.x * blockDim.x + threadIdx.x;
    if (i >= 384 * 4608) return;
    int n = i / 4608, k = i % 4608;
    float v = (n < INDIM) ? Wout[(size_t)k * FEAT + INDIM + n] : 0.f;
    __nv_bfloat16 h = __float2bfloat16(v);
    Bh[i] = h;
    Bl[i] = __float2bfloat16(v - __bfloat162float(h));
}

// ---------------- SRU recurrence: 1 thread/(b,h), depth-10 rolling prefetch ---
__global__ __launch_bounds__(64) void sru_scan(
    const float* __restrict__ U, const float* __restrict__ X,
    float* __restrict__ Xout,
    const float* __restrict__ v, const float* __restrict__ bb)
{
    int g = blockIdx.x * 64 + threadIdx.x;
    int b = g / H_, h = g % H_;
    const float vf = v[h],  vr = v[H_ + h];
    const float bf = bb[h], br = bb[H_ + h];
    const float* Ub = U + b * H3 + h;
    const float* Xb = X + b * H_ + h;
    float*       Ob = Xout + b * H_ + h;

    float pxt[PF], pfp[PF], prp[PF], pxin[PF];
    #pragma unroll
    for (int i = 0; i < PF; ++i) {
        const float* Un = Ub + (size_t)i * B_ * H3;
        pxt[i]  = Un[0]; pfp[i] = Un[H_]; prp[i] = Un[2 * H_];
        pxin[i] = Xb[(size_t)i * B_ * H_];
    }
    float c = 0.f;
    for (int t0 = 0; t0 < T_; t0 += PF) {
        #pragma unroll
        for (int i = 0; i < PF; ++i) {
            int t = t0 + i;
            float xt = pxt[i], fp = pfp[i], rp = prp[i], xin = pxin[i];
            int tp = t + PF;
            if (tp < T_) {
                const float* Un = Ub + (size_t)tp * B_ * H3;
                pxt[i]  = Un[0]; pfp[i] = Un[H_]; prp[i] = Un[2 * H_];
                pxin[i] = Xb[(size_t)tp * B_ * H_];
            }
            float f  = sigf(fp + vf * c + bf);
            float rr = sigf(rp + vr * c + br);
            float cn = f * c + (1.f - f) * xt;
            Ob[(size_t)t * B_ * H_] = rr * cn + (1.f - rr) * xin;
            c = cn;
        }
    }
}

// -------- fused conv 6x6 (9ch, pad 3/2) + bias + tanh + h-direction 3-max ----
__global__ __launch_bounds__(512) void conv_pool_h(
    const float* __restrict__ X, const float* __restrict__ Wk,
    const float* __restrict__ cb, float* __restrict__ out)
{
    __shared__ float sw[KN * KS * KS];
    __shared__ float xs[KS][H_ + 6];
    __shared__ float buf[KN][H_ + 2];

    int h = threadIdx.x;
    int t = blockIdx.x;
    int b = blockIdx.y;

    for (int i = h; i < KN * KS * KS; i += 512) sw[i] = Wk[i];

    #pragma unroll
    for (int p = 0; p < KS; ++p) {
        int tt = t - 3 + p;
        const float* rowp = X + (size_t)(tt * B_ + b) * H_;
        bool tok = (tt >= 0 && tt < T_);
        for (int idx = h; idx < H_ + 6; idx += 512) {
            int hh = idx - 3;
            xs[p][idx] = (tok && hh >= 0 && hh < H_) ? rowp[hh] : 0.f;
        }
    }
    if (h < KN) { buf[h][0] = -INFINITY; buf[h][H_ + 1] = -INFINITY; }
    __syncthreads();

    float acc[KN];
    #pragma unroll
    for (int o = 0; o < KN; ++o) acc[o] = 0.f;
    #pragma unroll
    for (int p = 0; p < KS; ++p) {
        float xv[KS];
        #pragma unroll
        for (int q = 0; q < KS; ++q) xv[q] = xs[p][h + q];
        #pragma unroll
        for (int q = 0; q < KS; ++q) {
            float x = xv[q];
            #pragma unroll
            for (int o = 0; o < KN; ++o)
                acc[o] = fmaf(x, sw[o * 36 + p * 6 + q], acc[o]);
        }
    }
    #pragma unroll
    for (int o = 0; o < KN; ++o) buf[o][h + 1] = tanhf(acc[o] + cb[o]);
    __syncthreads();

    #pragma unroll
    for (int o = 0; o < KN; ++o) {
        float m = fmaxf(fmaxf(buf[o][h], buf[o][h + 1]), buf[o][h + 2]);
        out[((size_t)(b * KN + o) * T_ + t) * H_ + h] = m;
    }
}

// t-direction max + transpose into (B*T, H*KN), feature = h*KN + o
__global__ void pool_t(const float* __restrict__ in, float* __restrict__ Y)
{
    int h  = blockIdx.x * blockDim.x + threadIdx.x;
    int t  = blockIdx.y;
    int bk = blockIdx.z;
    int b  = bk / KN, o = bk % KN;
    size_t base = ((size_t)bk * T_ + t) * H_ + h;
    float m = in[base];
    if (t > 0)      m = fmaxf(m, in[base - H_]);
    if (t < T_ - 1) m = fmaxf(m, in[base + H_]);
    Y[((size_t)(b * T_ + t)) * FOUT + h * KN + o] = m;
}

// ---------------- launch ------------------------------------------------------
extern "C" void kernel_launch(void* const* d_in, const int* in_sizes, int n_in,
                              void* d_out, int out_size)
{
    const float* inputs = (const float*)d_in[0];
    const float* W_in   = (const float*)d_in[1];
    const float* b_in   = (const float*)d_in[2];
    const float* W_rnn  = (const float*)d_in[3];
    const float* v_rnn  = (const float*)d_in[4];
    const float* b_rnn  = (const float*)d_in[5];
    const float* conv_k = (const float*)d_in[6];
    const float* conv_b = (const float*)d_in[7];
    const float* W_out  = (const float*)d_in[8];
    const float* b_out  = (const float*)d_in[9];
    float* out = (float*)d_out;

    float *X0, *U, *X1, *X2, *HM, *Y;
    __nv_bfloat16 *BinH, *BinL, *BrnnH, *BrnnL, *BoutH, *BoutL;
    cudaGetSymbolAddress((void**)&X0,   g_X0);
    cudaGetSymbolAddress((void**)&U,    g_U);
    cudaGetSymbolAddress((void**)&X1,   g_X1);
    cudaGetSymbolAddress((void**)&X2,   g_X2);
    cudaGetSymbolAddress((void**)&HM,   g_hmax);
    cudaGetSymbolAddress((void**)&Y,    g_Y);
    cudaGetSymbolAddress((void**)&BinH, g_BinH);
    cudaGetSymbolAddress((void**)&BinL, g_BinL);
    cudaGetSymbolAddress((void**)&BrnnH,g_BrnnH);
    cudaGetSymbolAddress((void**)&BrnnL,g_BrnnL);
    cudaGetSymbolAddress((void**)&BoutH,g_BoutH);
    cudaGetSymbolAddress((void**)&BoutL,g_BoutL);

    // weight prep (K-major bf16 hi/lo)
    prep_w<<<(512*800 + 255)/256, 256>>>(W_in, BinH, BinL, FEAT, H_, 800);
    prep_w<<<(1536*512 + 255)/256, 256>>>(W_rnn, BrnnH, BrnnL, H_, H3, 512);
    prep_w<<<(1536*512 + 255)/256, 256>>>(W_rnn + H_*H3, BrnnH + 1536*512,
                                          BrnnL + 1536*512, H_, H3, 512);
    prep_wout<<<(384*4608 + 255)/256, 256>>>(W_out, BoutH, BoutL);

    // input layer: tanh(inputs @ W_in + b_in) -> X0 (T,B,H)
    hgemm<1><<<dim3(4, 125), 256>>>(
        inputs, BinH, BinL, X0, FEAT, 800, FEAT, H_, H_, b_in, nullptr);

    // SRU layer 0
    hgemm<0><<<dim3(12, 125), 256>>>(
        X0, BrnnH, BrnnL, U, H_, 512, H_, H3, H3, nullptr, nullptr);
    sru_scan<<<(B_*H_)/64, 64>>>(U, X0, X1, v_rnn, b_rnn);

    // SRU layer 1
    hgemm<0><<<dim3(12, 125), 256>>>(
        X1, BrnnH + 1536*512, BrnnL + 1536*512, U, H_, 512, H_, H3, H3,
        nullptr, nullptr);
    sru_scan<<<(B_*H_)/64, 64>>>(U, X1, X2, v_rnn + 2*H_, b_rnn + 2*H_);

    // fused conv + bias + tanh + h-pool
    conv_pool_h<<<dim3(T_, B_), 512>>>(X2, conv_k, conv_b, HM);

    // t-pool + transpose to (B*T, H*KN)
    pool_t<<<dim3(H_/256, T_, B_*KN), 256>>>(HM, Y);

    // output GEMM (257 live cols, padded to 384) + sigmoid gate * inputs
    hgemm<2><<<dim3(3, 125), 256>>>(
        Y, BoutH, BoutL, out, FOUT, FOUT, FOUT, INDIM, INDIM,
        b_out + INDIM, inputs);
}